// round 10
// baseline (speedup 1.0000x reference)
#include <cuda_runtime.h>
#include <math.h>

#define FULL 0xffffffffu

// ---------------------------------------------------------------------------
// Closed form (verified rounds 1-9): fold the trailing CNOT ring into the
// PauliZ masks; the measured state is a product state, so
//   <Z_w> = prod_{q in M_w} z_q,  M_w = {0..w} (w>=1), M_0 = {1..9}
//   RX-circuit: z = cos(h + theta) ; RY-circuit: z = cos(theta)*cos(h)
//
// Layout: 8 threads/row octet, 1 row/thread-slice, 4 rows/warp,
// 1024 blocks x 128 threads (131072 threads), single launch.
// GEMM: packed fma.rn.f32x2 on LDG.128 payloads (80 FFMA2).
// Reduce: xor-1 full (10 shfl) -> keep parity half -> xor-2/xor-4 on 5 (10).
// Epilogue ownership (even lanes hold h[0..4], odd h[5..9]):
//   q0:{0,1,2}  q1:{5,6,7}  q2:{3,4}  q3:{8,9}   (all quad lanes active)
// Wire-order for prefix products: [q0, q2, q1, q3]; 3-shfl xor-gather.
// ---------------------------------------------------------------------------

__device__ __forceinline__ unsigned long long
fma_f32x2(unsigned long long a, unsigned long long bb, unsigned long long c) {
    unsigned long long d;
    asm("fma.rn.f32x2 %0, %1, %2, %3;" : "=l"(d) : "l"(a), "l"(bb), "l"(c));
    return d;
}

__global__ void __launch_bounds__(128)
qlstm_kernel(const float* __restrict__ x, const float* __restrict__ W,
             const float* __restrict__ b,
             const float* __restrict__ wf, const float* __restrict__ wi,
             const float* __restrict__ wu, const float* __restrict__ wo,
             float* __restrict__ out) {
    const int tid = threadIdx.x;
    const int oc  = tid & 7;                   // eighth within row
    const int row = (blockIdx.x * 128 + tid) >> 3;

    // ---- front-batched x loads: row = 32 x 16B granules ----
    const longlong2* xp = reinterpret_cast<const longlong2*>(x) + (size_t)row * 32;
    longlong2 xv[4];
#pragma unroll
    for (int i = 0; i < 4; i++) xv[i] = xp[i * 8 + oc];

    // ---- GEMM: h = x[row] @ W^T, packed f32x2 FMA ----
    const longlong2* Wp = reinterpret_cast<const longlong2*>(W);
    unsigned long long acc2[10];
#pragma unroll
    for (int o = 0; o < 10; o++) acc2[o] = 0ull;
#pragma unroll
    for (int i = 0; i < 4; i++) {
        const unsigned long long xlo = (unsigned long long)xv[i].x;
        const unsigned long long xhi = (unsigned long long)xv[i].y;
#pragma unroll
        for (int o = 0; o < 10; o++) {
            const longlong2 wv = __ldg(&Wp[o * 32 + i * 8 + oc]);
            acc2[o] = fma_f32x2(xlo, (unsigned long long)wv.x, acc2[o]);
            acc2[o] = fma_f32x2(xhi, (unsigned long long)wv.y, acc2[o]);
        }
    }
    float acc[10];
#pragma unroll
    for (int o = 0; o < 10; o++) {
        const float lo = __uint_as_float((unsigned)(acc2[o] & 0xffffffffull));
        const float hi = __uint_as_float((unsigned)(acc2[o] >> 32));
        acc[o] = lo + hi;
    }

    // ---- reduce: full xor-1, then parity-split halves for xor-2/xor-4 ----
#pragma unroll
    for (int o = 0; o < 10; o++) acc[o] += __shfl_xor_sync(FULL, acc[o], 1);

    const int p = oc & 1;                      // 0: outputs 0-4, 1: outputs 5-9
    float a[5];
#pragma unroll
    for (int j = 0; j < 5; j++) a[j] = p ? acc[5 + j] : acc[j];
#pragma unroll
    for (int j = 0; j < 5; j++) a[j] += __shfl_xor_sync(FULL, a[j], 2);
#pragma unroll
    for (int j = 0; j < 5; j++) a[j] += __shfl_xor_sync(FULL, a[j], 4);
    // now: even lanes hold h[0..4], odd lanes h[5..9] (complete sums)

    // ---- quad epilogue: q0:{0,1,2} q1:{5,6,7} q2:{3,4} q3:{8,9} ----
    const int lane = tid & 31;
    const int q = lane & 3;
    const int nw = (q < 2) ? 3 : 2;
    const int j0 = (q < 2) ? 0 : 3;            // index into a[]
    const int w0 = 5 * p + j0;                 // first owned wire

    float myh[3], zf[3], zi[3], zu[3], zo[3];
#pragma unroll
    for (int j = 0; j < 3; j++) {
        if (j < nw) {
            const int w = w0 + j;
            const float h = ((j0 == 0) ? a[j] : a[3 + j]) + __ldg(b + w);
            myh[j] = h;
            const float ch = __cosf(h);
            zf[j] = __cosf(h + __ldg(wf + w));          // RX: cos(h + wf)
            zi[j] = __cosf(__ldg(wi + w)) * ch;         // RY: cos(wi)*cos(h)
            zu[j] = __cosf(h + __ldg(wu + w));
            zo[j] = __cosf(h + __ldg(wo + w));
        } else {
            myh[j] = 0.0f;
            zf[j] = zi[j] = zu[j] = zo[j] = 1.0f;
        }
    }

    // prefix composition along wire-order [q0, q2, q1, q3]:
    //   C(q0)=1; C(q2)=x2; C(q1)=x1*x3; C(q3)=x1*x2*x3
    // wire-0 special (q0): E0 = z1*z2 * x1*x2*x3
    float Ef[3], Ei[3], Eu[3], Eo[3];
#pragma unroll
    for (int c = 0; c < 4; c++) {
        const float* z = (c == 0) ? zf : (c == 1) ? zi : (c == 2) ? zu : zo;
        const float l1 = z[0], l2 = l1 * z[1], l3 = l2 * z[2];
        const float l  = (q < 2) ? l3 : l2;             // product of owned z's

        const float x1 = __shfl_xor_sync(FULL, l, 1);
        const float x2 = __shfl_xor_sync(FULL, l, 2);
        const float x3 = __shfl_xor_sync(FULL, x1, 2);
        const float p123 = x1 * x2 * x3;
        const float C = (q == 0) ? 1.0f : (q == 2) ? x2
                       : (q == 1) ? x1 * x3 : p123;

        float E0 = C * l1;
        if (q == 0) E0 = z[1] * z[2] * p123;            // wire 0: z1..z9
        const float E1 = C * l2, E2 = C * l3;

        if (c == 0)      { Ef[0] = E0; Ef[1] = E1; Ef[2] = E2; }
        else if (c == 1) { Ei[0] = E0; Ei[1] = E1; Ei[2] = E2; }
        else if (c == 2) { Eu[0] = E0; Eu[1] = E1; Eu[2] = E2; }
        else             { Eo[0] = E0; Eo[1] = E1; Eo[2] = E2; }
    }

    // ---- LSTM epilogue; only the low quad of each octet stores ----
    const bool writer = (lane & 4) == 0;
#pragma unroll
    for (int j = 0; j < 3; j++) {
        if (j < nw && writer) {
            const float ing = __fdividef(1.0f, 1.0f + __expf(-Ef[j]));
            const float fg  = __fdividef(1.0f, 1.0f + __expf(-Ei[j]));
            const float cg  = __fdividef(2.0f, 1.0f + __expf(-2.0f * Eu[j])) - 1.0f;
            const float og  = __fdividef(1.0f, 1.0f + __expf(-Eo[j]));
            const float nh  = fmaf(myh[j], fg, ing * cg);
            const float th  = __fdividef(2.0f, 1.0f + __expf(-2.0f * nh)) - 1.0f;
            out[row * 10 + w0 + j] = og * th;
        }
    }
}

extern "C" void kernel_launch(void* const* d_in, const int* in_sizes, int n_in,
                              void* d_out, int out_size) {
    const float* x  = (const float*)d_in[0];
    const float* W  = (const float*)d_in[1];
    const float* b  = (const float*)d_in[2];
    const float* wf = (const float*)d_in[3];
    const float* wi = (const float*)d_in[4];
    const float* wu = (const float*)d_in[5];
    const float* wo = (const float*)d_in[6];
    float* out = (float*)d_out;

    // 16384 rows x 8 threads = 131072 threads; 128/block -> 1024 blocks
    qlstm_kernel<<<1024, 128>>>(x, W, b, wf, wi, wu, wo, out);
}